// round 1
// baseline (speedup 1.0000x reference)
#include <cuda_runtime.h>
#include <math.h>

#define BB   2
#define SS   2048
#define DM   2048
#define HQn  32
#define HKVn 8
#define DHn  64
#define Gn   4
#define ROWS (BB * SS)          // 4096
#define DKV  (HKVn * DHn)       // 512

// Scratch (no allocations allowed anywhere)
__device__ float g_Q[ROWS * DM];      // projected Q  [b,s,hq,d] = [4096,2048]
__device__ float g_K[ROWS * DKV];     // projected K  [b,s,hk,d] = [4096,512]
__device__ float g_V[ROWS * DKV];     // projected V
__device__ float g_C[ROWS * DM];      // attention context (pre-Wo)

// ---------------------------------------------------------------------------
// SGEMM: C[M,N] = A[M,K] @ B[K,N], all row-major. BM=BN=128, BK=8,
// 256 threads, 8x8 per-thread micro-tile. M,N,K multiples of 128 here.
// ---------------------------------------------------------------------------
__global__ __launch_bounds__(256)
void sgemm128(const float* __restrict__ A, const float* __restrict__ Bm,
              float* __restrict__ C, int M, int N, int K)
{
    __shared__ float As[8][128];   // k-major: As[k][m]
    __shared__ float Bs[8][128];   // Bs[k][n]

    const int tid = threadIdx.x;
    const int tx  = tid & 15;        // 0..15  (n dir)
    const int ty  = tid >> 4;        // 0..15  (m dir)
    const int m0  = blockIdx.y * 128;
    const int n0  = blockIdx.x * 128;

    // global-load assignments
    const int arow = tid >> 1;           // 0..127
    const int acol = (tid & 1) << 2;     // 0 or 4
    const int brow = tid >> 5;           // 0..7
    const int bcol = (tid & 31) << 2;    // 0..124

    const float* Ap = A  + (size_t)(m0 + arow) * K + acol;
    const float* Bp = Bm + (size_t)brow * N + n0 + bcol;

    float acc[8][8];
#pragma unroll
    for (int i = 0; i < 8; i++)
#pragma unroll
        for (int j = 0; j < 8; j++) acc[i][j] = 0.0f;

    for (int k0 = 0; k0 < K; k0 += 8) {
        float4 av = *(const float4*)(Ap + k0);
        float4 bv = *(const float4*)(Bp + (size_t)k0 * N);
        __syncthreads();
        As[acol + 0][arow] = av.x;
        As[acol + 1][arow] = av.y;
        As[acol + 2][arow] = av.z;
        As[acol + 3][arow] = av.w;
        *(float4*)&Bs[brow][bcol] = bv;
        __syncthreads();

#pragma unroll
        for (int kk = 0; kk < 8; kk++) {
            float a[8], b[8];
            *(float4*)&a[0] = *(const float4*)&As[kk][ty * 4];
            *(float4*)&a[4] = *(const float4*)&As[kk][ty * 4 + 64];
            *(float4*)&b[0] = *(const float4*)&Bs[kk][tx * 4];
            *(float4*)&b[4] = *(const float4*)&Bs[kk][tx * 4 + 64];
#pragma unroll
            for (int i = 0; i < 8; i++)
#pragma unroll
                for (int j = 0; j < 8; j++)
                    acc[i][j] += a[i] * b[j];
        }
    }

#pragma unroll
    for (int i = 0; i < 8; i++) {
        int r = m0 + ((i < 4) ? (ty * 4 + i) : (64 + ty * 4 + (i - 4)));
        float4 v0 = make_float4(acc[i][0], acc[i][1], acc[i][2], acc[i][3]);
        float4 v1 = make_float4(acc[i][4], acc[i][5], acc[i][6], acc[i][7]);
        *(float4*)(C + (size_t)r * N + n0 + tx * 4)      = v0;
        *(float4*)(C + (size_t)r * N + n0 + tx * 4 + 64) = v1;
    }
}

// ---------------------------------------------------------------------------
// Flash attention (non-causal, GQA). One block per (64-query tile, head).
// 256 threads as 16x16: thread owns 4 query rows (4*ty..), score cols
// {tx, tx+16} (32-key tile), ctx cols {tx,tx+16,tx+32,tx+48}.
// Padded smem strides (65/33) -> conflict-free column reads.
// ---------------------------------------------------------------------------
__global__ __launch_bounds__(256)
void attn64(const float* __restrict__ Qp, const float* __restrict__ Kp,
            const float* __restrict__ Vp, float* __restrict__ Cp)
{
    __shared__ float Qs[64][65];
    __shared__ float Ks[32][65];
    __shared__ float Vs[32][65];
    __shared__ float Ps[64][33];

    const int tid = threadIdx.x;
    const int tx  = tid & 15;
    const int ty  = tid >> 4;
    const int head = blockIdx.y;        // 0..63
    const int b   = head >> 5;          // /32
    const int hq  = head & 31;
    const int hk  = hq >> 2;            // hq / G
    const int sq0 = blockIdx.x << 6;

    const float* Qb = Qp + ((size_t)b * SS + sq0) * DM + hq * DHn;
    const float* Kb = Kp + (size_t)b * SS * DKV + hk * DHn;
    const float* Vb = Vp + (size_t)b * SS * DKV + hk * DHn;

    const float scale = 0.125f;  // 1/sqrt(64)

    // load Q tile, pre-scaled
    for (int i = tid; i < 64 * 64; i += 256) {
        int r = i >> 6, c = i & 63;
        Qs[r][c] = Qb[(size_t)r * DM + c] * scale;
    }

    float m[4], l[4], acc[4][4];
#pragma unroll
    for (int i = 0; i < 4; i++) {
        m[i] = -1e30f; l[i] = 0.0f;
#pragma unroll
        for (int j = 0; j < 4; j++) acc[i][j] = 0.0f;
    }

    for (int kt = 0; kt < SS / 32; kt++) {
        const int k0 = kt << 5;
        __syncthreads();   // prior tile's P@V done before overwriting Ks/Vs/Ps
        for (int i = tid; i < 32 * 64; i += 256) {
            int r = i >> 6, c = i & 63;
            size_t off = (size_t)(k0 + r) * DKV + c;
            Ks[r][c] = Kb[off];
            Vs[r][c] = Vb[off];
        }
        __syncthreads();

        // S = Q @ K^T  (Q pre-scaled)
        float s[4][2] = {{0.f,0.f},{0.f,0.f},{0.f,0.f},{0.f,0.f}};
#pragma unroll 4
        for (int d = 0; d < 64; d++) {
            float qv0 = Qs[ty * 4 + 0][d];
            float qv1 = Qs[ty * 4 + 1][d];
            float qv2 = Qs[ty * 4 + 2][d];
            float qv3 = Qs[ty * 4 + 3][d];
            float kv0 = Ks[tx][d];
            float kv1 = Ks[tx + 16][d];
            s[0][0] += qv0 * kv0;  s[0][1] += qv0 * kv1;
            s[1][0] += qv1 * kv0;  s[1][1] += qv1 * kv1;
            s[2][0] += qv2 * kv0;  s[2][1] += qv2 * kv1;
            s[3][0] += qv3 * kv0;  s[3][1] += qv3 * kv1;
        }

        // online softmax per query row (row spread across 16 lanes, same half-warp)
#pragma unroll
        for (int i = 0; i < 4; i++) {
            float rm = fmaxf(s[i][0], s[i][1]);
            rm = fmaxf(rm, __shfl_xor_sync(0xffffffffu, rm, 1));
            rm = fmaxf(rm, __shfl_xor_sync(0xffffffffu, rm, 2));
            rm = fmaxf(rm, __shfl_xor_sync(0xffffffffu, rm, 4));
            rm = fmaxf(rm, __shfl_xor_sync(0xffffffffu, rm, 8));
            float mn    = fmaxf(m[i], rm);
            float alpha = __expf(m[i] - mn);
            float p0 = __expf(s[i][0] - mn);
            float p1 = __expf(s[i][1] - mn);
            float rs = p0 + p1;
            rs += __shfl_xor_sync(0xffffffffu, rs, 1);
            rs += __shfl_xor_sync(0xffffffffu, rs, 2);
            rs += __shfl_xor_sync(0xffffffffu, rs, 4);
            rs += __shfl_xor_sync(0xffffffffu, rs, 8);
            l[i] = l[i] * alpha + rs;
            m[i] = mn;
#pragma unroll
            for (int j = 0; j < 4; j++) acc[i][j] *= alpha;
            Ps[ty * 4 + i][tx]      = p0;
            Ps[ty * 4 + i][tx + 16] = p1;
        }
        __syncthreads();

        // ctx += P @ V
#pragma unroll 4
        for (int k = 0; k < 32; k++) {
            float pv0 = Ps[ty * 4 + 0][k];
            float pv1 = Ps[ty * 4 + 1][k];
            float pv2 = Ps[ty * 4 + 2][k];
            float pv3 = Ps[ty * 4 + 3][k];
            float vv0 = Vs[k][tx];
            float vv1 = Vs[k][tx + 16];
            float vv2 = Vs[k][tx + 32];
            float vv3 = Vs[k][tx + 48];
            acc[0][0] += pv0 * vv0; acc[0][1] += pv0 * vv1; acc[0][2] += pv0 * vv2; acc[0][3] += pv0 * vv3;
            acc[1][0] += pv1 * vv0; acc[1][1] += pv1 * vv1; acc[1][2] += pv1 * vv2; acc[1][3] += pv1 * vv3;
            acc[2][0] += pv2 * vv0; acc[2][1] += pv2 * vv1; acc[2][2] += pv2 * vv2; acc[2][3] += pv2 * vv3;
            acc[3][0] += pv3 * vv0; acc[3][1] += pv3 * vv1; acc[3][2] += pv3 * vv2; acc[3][3] += pv3 * vv3;
        }
    }

    // epilogue: normalize, write ctx in [b,s,hq,d] layout (== [b,s,2048])
    float* Ob = Cp + ((size_t)b * SS + sq0) * DM + hq * DHn;
#pragma unroll
    for (int i = 0; i < 4; i++) {
        float inv = 1.0f / l[i];
#pragma unroll
        for (int j = 0; j < 4; j++)
            Ob[(size_t)(ty * 4 + i) * DM + tx + 16 * j] = acc[i][j] * inv;
    }
}

// ---------------------------------------------------------------------------
extern "C" void kernel_launch(void* const* d_in, const int* in_sizes, int n_in,
                              void* d_out, int out_size)
{
    const float* q  = (const float*)d_in[0];
    const float* k  = (const float*)d_in[1];
    const float* v  = (const float*)d_in[2];
    const float* Wq = (const float*)d_in[3];
    const float* Wk = (const float*)d_in[4];
    const float* Wv = (const float*)d_in[5];
    const float* Wo = (const float*)d_in[6];
    float* out = (float*)d_out;

    float *Qd, *Kd, *Vd, *Cd;
    cudaGetSymbolAddress((void**)&Qd, g_Q);
    cudaGetSymbolAddress((void**)&Kd, g_K);
    cudaGetSymbolAddress((void**)&Vd, g_V);
    cudaGetSymbolAddress((void**)&Cd, g_C);

    dim3 blk(256);
    // Projections
    sgemm128<<<dim3(DM  / 128, ROWS / 128), blk>>>(q, Wq, Qd, ROWS, DM,  DM);
    sgemm128<<<dim3(DKV / 128, ROWS / 128), blk>>>(k, Wk, Kd, ROWS, DKV, DM);
    sgemm128<<<dim3(DKV / 128, ROWS / 128), blk>>>(v, Wv, Vd, ROWS, DKV, DM);
    // Attention
    attn64<<<dim3(SS / 64, BB * HQn), blk>>>(Qd, Kd, Vd, Cd);
    // Output projection
    sgemm128<<<dim3(DM / 128, ROWS / 128), blk>>>(Cd, Wo, out, ROWS, DM, DM);
}

// round 3
// speedup vs baseline: 1.4655x; 1.4655x over previous
#include <cuda_runtime.h>
#include <cuda_bf16.h>
#include <cstdint>
#include <math.h>

#define BB   2
#define SS   2048
#define DM   2048
#define HQn  32
#define HKVn 8
#define DHn  64
#define ROWS (BB * SS)          // 4096
#define DKV  (HKVn * DHn)       // 512
#define KDIM 2048

// ---------------- scratch ----------------
__device__ float g_Q[ROWS * DM];
__device__ float g_K[ROWS * DKV];
__device__ float g_V[ROWS * DKV];
__device__ float g_C[ROWS * DM];
__device__ __nv_bfloat16 g_Whi[DM * DM];   // transposed weight hi [N][K]
__device__ __nv_bfloat16 g_Wlo[DM * DM];   // transposed weight lo [N][K]

// ---------------- helpers ----------------
__device__ __forceinline__ uint32_t smem_u32(const void* p) {
    uint32_t r;
    asm("{ .reg .u64 t; cvta.to.shared.u64 t, %1; cvt.u32.u64 %0, t; }" : "=r"(r) : "l"(p));
    return r;
}
__device__ __forceinline__ uint32_t packbf(float x0, float x1) {
    // mem order: low half = x0
    uint32_t r;
    asm("cvt.rn.bf16x2.f32 %0, %1, %2;" : "=r"(r) : "f"(x1), "f"(x0));
    return r;
}
__device__ __forceinline__ void sts64(uint32_t a, uint32_t x, uint32_t y) {
    asm volatile("st.shared.v2.b32 [%0], {%1,%2};" :: "r"(a), "r"(x), "r"(y));
}
__device__ __forceinline__ void sts128(uint32_t a, uint4 v) {
    asm volatile("st.shared.v4.b32 [%0], {%1,%2,%3,%4};"
                 :: "r"(a), "r"(v.x), "r"(v.y), "r"(v.z), "r"(v.w));
}
__device__ __forceinline__ void ldsm4(uint32_t a, uint32_t r[4]) {
    asm volatile("ldmatrix.sync.aligned.m8n8.x4.shared.b16 {%0,%1,%2,%3}, [%4];"
                 : "=r"(r[0]), "=r"(r[1]), "=r"(r[2]), "=r"(r[3]) : "r"(a));
}
__device__ __forceinline__ void mma_bf16(float c[4], const uint32_t a[4], const uint32_t b[2]) {
    asm volatile("mma.sync.aligned.m16n8k16.row.col.f32.bf16.bf16.f32 "
                 "{%0,%1,%2,%3},{%4,%5,%6,%7},{%8,%9},{%0,%1,%2,%3};"
                 : "+f"(c[0]), "+f"(c[1]), "+f"(c[2]), "+f"(c[3])
                 : "r"(a[0]), "r"(a[1]), "r"(a[2]), "r"(a[3]), "r"(b[0]), "r"(b[1]));
}

// ---------------------------------------------------------------------------
// Weight transpose + bf16 hi/lo split
// ---------------------------------------------------------------------------
__global__ __launch_bounds__(256)
void wconv(const float* __restrict__ W, __nv_bfloat16* __restrict__ Whi,
           __nv_bfloat16* __restrict__ Wlo, int N)
{
    __shared__ float t[32][33];
    int n0 = blockIdx.x * 32, k0 = blockIdx.y * 32;
    int tx = threadIdx.x, ty = threadIdx.y;   // 32 x 8
#pragma unroll
    for (int i = ty; i < 32; i += 8)
        t[i][tx] = W[(size_t)(k0 + i) * N + n0 + tx];
    __syncthreads();
#pragma unroll
    for (int i = ty; i < 32; i += 8) {
        float x = t[tx][i];
        __nv_bfloat16 h = __float2bfloat16(x);
        float hf = __bfloat162float(h);
        Whi[(size_t)(n0 + i) * KDIM + k0 + tx] = h;
        Wlo[(size_t)(n0 + i) * KDIM + k0 + tx] = __float2bfloat16(x - hf);
    }
}

// ---------------------------------------------------------------------------
// HMMA GEMM: C[4096,N] = A[4096,2048](fp32) @ Wt(split bf16 [N][K])
// 128x128 tile, BK=32, double-buffered smem, 3-term bf16 split.
// smem per stage: Ah,Al,Bh,Bl each [128][40] bf16 (80B rows) = 40960 B
// ---------------------------------------------------------------------------
#define ST_SZ   40960
#define A_OFF   0
#define AL_OFF  10240
#define BH_OFF  20480
#define BL_OFF  30720
#define GEMM_SMEM (2 * ST_SZ)   // 81920

__global__ __launch_bounds__(256)
void gemm_hmma(const float* __restrict__ A, const __nv_bfloat16* __restrict__ Bhi,
               const __nv_bfloat16* __restrict__ Blo, float* __restrict__ C, int N)
{
    extern __shared__ char smem[];
    const uint32_t sb = smem_u32(smem);
    const int tid = threadIdx.x;
    const int wid = tid >> 5, lane = tid & 31;
    const int wm = wid >> 2, wn = wid & 3;     // 2 x 4 warps
    const int m0 = blockIdx.y * 128, n0 = blockIdx.x * 128;

    // global-load mapping
    const int arow = tid >> 3, acol = (tid & 7) * 4;   // A: 4 rows stride 32
    const int brow = tid >> 2, bcol = (tid & 3) * 8;   // B: 2 rows stride 64

    const float* Ab = A + (size_t)(m0 + arow) * KDIM + acol;
    const __nv_bfloat16* Bhb = Bhi + (size_t)(n0 + brow) * KDIM + bcol;
    const __nv_bfloat16* Blb = Blo + (size_t)(n0 + brow) * KDIM + bcol;

    // ldmatrix base offsets (within stage)
    const uint32_t aRow = (uint32_t)(wm * 64 + (lane & 15)) * 80 + (lane >> 4) * 16;
    const uint32_t bRow = (uint32_t)(wn * 32 + (lane & 7) + (lane >> 4) * 8) * 80
                        + ((lane >> 3) & 1) * 16;

    float acc[4][4][4];
#pragma unroll
    for (int i = 0; i < 4; i++)
#pragma unroll
        for (int j = 0; j < 4; j++)
#pragma unroll
            for (int r = 0; r < 4; r++) acc[i][j][r] = 0.0f;

    float4 fa[4];
    uint4  fbh[2], fbl[2];

    // ---- prologue: load k-chunk 0 ----
#pragma unroll
    for (int p = 0; p < 4; p++) fa[p] = *(const float4*)(Ab + (size_t)(p * 32) * KDIM);
#pragma unroll
    for (int p = 0; p < 2; p++) {
        fbh[p] = *(const uint4*)(Bhb + (size_t)(p * 64) * KDIM);
        fbl[p] = *(const uint4*)(Blb + (size_t)(p * 64) * KDIM);
    }

    auto store_stage = [&](uint32_t st) {
#pragma unroll
        for (int p = 0; p < 4; p++) {
            uint32_t ad = st + (uint32_t)(arow + p * 32) * 80 + acol * 2;
            float x0 = fa[p].x, x1 = fa[p].y, x2 = fa[p].z, x3 = fa[p].w;
            float h0 = __bfloat162float(__float2bfloat16(x0));
            float h1 = __bfloat162float(__float2bfloat16(x1));
            float h2 = __bfloat162float(__float2bfloat16(x2));
            float h3 = __bfloat162float(__float2bfloat16(x3));
            sts64(ad + A_OFF,  packbf(x0, x1), packbf(x2, x3));
            sts64(ad + AL_OFF, packbf(x0 - h0, x1 - h1), packbf(x2 - h2, x3 - h3));
        }
#pragma unroll
        for (int p = 0; p < 2; p++) {
            uint32_t bd = st + (uint32_t)(brow + p * 64) * 80 + bcol * 2;
            sts128(bd + BH_OFF, fbh[p]);
            sts128(bd + BL_OFF, fbl[p]);
        }
    };

    store_stage(sb);
    __syncthreads();

    const int NIT = KDIM / 32;
    for (int c = 0; c < NIT; c++) {
        const uint32_t st = sb + (uint32_t)(c & 1) * ST_SZ;

        // prefetch next chunk
        if (c + 1 < NIT) {
            int kc = (c + 1) * 32;
#pragma unroll
            for (int p = 0; p < 4; p++)
                fa[p] = *(const float4*)(Ab + (size_t)(p * 32) * KDIM + kc);
#pragma unroll
            for (int p = 0; p < 2; p++) {
                fbh[p] = *(const uint4*)(Bhb + (size_t)(p * 64) * KDIM + kc);
                fbl[p] = *(const uint4*)(Blb + (size_t)(p * 64) * KDIM + kc);
            }
        }

        // compute this chunk: 2 k16 steps
#pragma unroll
        for (int ks = 0; ks < 2; ks++) {
            const uint32_t ko = ks * 32;
            uint32_t ah[4][4], bh[4][2], tmpv[4];
#pragma unroll
            for (int mi = 0; mi < 4; mi++)
                ldsm4(st + A_OFF + aRow + mi * 1280 + ko, ah[mi]);
#pragma unroll
            for (int j = 0; j < 2; j++) {
                ldsm4(st + BH_OFF + bRow + j * 1280 + ko, tmpv);
                bh[2*j][0] = tmpv[0]; bh[2*j][1] = tmpv[1];
                bh[2*j+1][0] = tmpv[2]; bh[2*j+1][1] = tmpv[3];
            }
#pragma unroll
            for (int mi = 0; mi < 4; mi++)
#pragma unroll
                for (int nj = 0; nj < 4; nj++)
                    mma_bf16(acc[mi][nj], ah[mi], bh[nj]);

            uint32_t bl[4][2];
#pragma unroll
            for (int j = 0; j < 2; j++) {
                ldsm4(st + BL_OFF + bRow + j * 1280 + ko, tmpv);
                bl[2*j][0] = tmpv[0]; bl[2*j][1] = tmpv[1];
                bl[2*j+1][0] = tmpv[2]; bl[2*j+1][1] = tmpv[3];
            }
#pragma unroll
            for (int mi = 0; mi < 4; mi++)
#pragma unroll
                for (int nj = 0; nj < 4; nj++)
                    mma_bf16(acc[mi][nj], ah[mi], bl[nj]);

            uint32_t al[4][4];
#pragma unroll
            for (int mi = 0; mi < 4; mi++)
                ldsm4(st + AL_OFF + aRow + mi * 1280 + ko, al[mi]);
#pragma unroll
            for (int mi = 0; mi < 4; mi++)
#pragma unroll
                for (int nj = 0; nj < 4; nj++)
                    mma_bf16(acc[mi][nj], al[mi], bh[nj]);
        }

        // stage next chunk
        if (c + 1 < NIT) {
            store_stage(sb + (uint32_t)((c + 1) & 1) * ST_SZ);
        }
        __syncthreads();
    }

    // ---- epilogue ----
    const int rbase = m0 + wm * 64 + (lane >> 2);
    const int cbase = n0 + wn * 32 + (lane & 3) * 2;
#pragma unroll
    for (int mi = 0; mi < 4; mi++)
#pragma unroll
        for (int nj = 0; nj < 4; nj++) {
            int r0 = rbase + mi * 16;
            int cc = cbase + nj * 8;
            *(float2*)(C + (size_t)r0 * N + cc)       = make_float2(acc[mi][nj][0], acc[mi][nj][1]);
            *(float2*)(C + (size_t)(r0 + 8) * N + cc) = make_float2(acc[mi][nj][2], acc[mi][nj][3]);
        }
}

// ---------------------------------------------------------------------------
// Flash attention (fp32, unchanged)
// ---------------------------------------------------------------------------
__global__ __launch_bounds__(256)
void attn64(const float* __restrict__ Qp, const float* __restrict__ Kp,
            const float* __restrict__ Vp, float* __restrict__ Cp)
{
    __shared__ float Qs[64][65];
    __shared__ float Ks[32][65];
    __shared__ float Vs[32][65];
    __shared__ float Ps[64][33];

    const int tid = threadIdx.x;
    const int tx  = tid & 15;
    const int ty  = tid >> 4;
    const int head = blockIdx.y;
    const int b   = head >> 5;
    const int hq  = head & 31;
    const int hk  = hq >> 2;
    const int sq0 = blockIdx.x << 6;

    const float* Qb = Qp + ((size_t)b * SS + sq0) * DM + hq * DHn;
    const float* Kb = Kp + (size_t)b * SS * DKV + hk * DHn;
    const float* Vb = Vp + (size_t)b * SS * DKV + hk * DHn;

    const float scale = 0.125f;

    for (int i = tid; i < 64 * 64; i += 256) {
        int r = i >> 6, c = i & 63;
        Qs[r][c] = Qb[(size_t)r * DM + c] * scale;
    }

    float m[4], l[4], acc[4][4];
#pragma unroll
    for (int i = 0; i < 4; i++) {
        m[i] = -1e30f; l[i] = 0.0f;
#pragma unroll
        for (int j = 0; j < 4; j++) acc[i][j] = 0.0f;
    }

    for (int kt = 0; kt < SS / 32; kt++) {
        const int k0 = kt << 5;
        __syncthreads();
        for (int i = tid; i < 32 * 64; i += 256) {
            int r = i >> 6, c = i & 63;
            size_t off = (size_t)(k0 + r) * DKV + c;
            Ks[r][c] = Kb[off];
            Vs[r][c] = Vb[off];
        }
        __syncthreads();

        float s[4][2] = {{0.f,0.f},{0.f,0.f},{0.f,0.f},{0.f,0.f}};
#pragma unroll 4
        for (int d = 0; d < 64; d++) {
            float qv0 = Qs[ty * 4 + 0][d];
            float qv1 = Qs[ty * 4 + 1][d];
            float qv2 = Qs[ty * 4 + 2][d];
            float qv3 = Qs[ty * 4 + 3][d];
            float kv0 = Ks[tx][d];
            float kv1 = Ks[tx + 16][d];
            s[0][0] += qv0 * kv0;  s[0][1] += qv0 * kv1;
            s[1][0] += qv1 * kv0;  s[1][1] += qv1 * kv1;
            s[2][0] += qv2 * kv0;  s[2][1] += qv2 * kv1;
            s[3][0] += qv3 * kv0;  s[3][1] += qv3 * kv1;
        }

#pragma unroll
        for (int i = 0; i < 4; i++) {
            float rm = fmaxf(s[i][0], s[i][1]);
            rm = fmaxf(rm, __shfl_xor_sync(0xffffffffu, rm, 1));
            rm = fmaxf(rm, __shfl_xor_sync(0xffffffffu, rm, 2));
            rm = fmaxf(rm, __shfl_xor_sync(0xffffffffu, rm, 4));
            rm = fmaxf(rm, __shfl_xor_sync(0xffffffffu, rm, 8));
            float mn    = fmaxf(m[i], rm);
            float alpha = __expf(m[i] - mn);
            float p0 = __expf(s[i][0] - mn);
            float p1 = __expf(s[i][1] - mn);
            float rs = p0 + p1;
            rs += __shfl_xor_sync(0xffffffffu, rs, 1);
            rs += __shfl_xor_sync(0xffffffffu, rs, 2);
            rs += __shfl_xor_sync(0xffffffffu, rs, 4);
            rs += __shfl_xor_sync(0xffffffffu, rs, 8);
            l[i] = l[i] * alpha + rs;
            m[i] = mn;
#pragma unroll
            for (int j = 0; j < 4; j++) acc[i][j] *= alpha;
            Ps[ty * 4 + i][tx]      = p0;
            Ps[ty * 4 + i][tx + 16] = p1;
        }
        __syncthreads();

#pragma unroll 4
        for (int k = 0; k < 32; k++) {
            float pv0 = Ps[ty * 4 + 0][k];
            float pv1 = Ps[ty * 4 + 1][k];
            float pv2 = Ps[ty * 4 + 2][k];
            float pv3 = Ps[ty * 4 + 3][k];
            float vv0 = Vs[k][tx];
            float vv1 = Vs[k][tx + 16];
            float vv2 = Vs[k][tx + 32];
            float vv3 = Vs[k][tx + 48];
            acc[0][0] += pv0 * vv0; acc[0][1] += pv0 * vv1; acc[0][2] += pv0 * vv2; acc[0][3] += pv0 * vv3;
            acc[1][0] += pv1 * vv0; acc[1][1] += pv1 * vv1; acc[1][2] += pv1 * vv2; acc[1][3] += pv1 * vv3;
            acc[2][0] += pv2 * vv0; acc[2][1] += pv2 * vv1; acc[2][2] += pv2 * vv2; acc[2][3] += pv2 * vv3;
            acc[3][0] += pv3 * vv0; acc[3][1] += pv3 * vv1; acc[3][2] += pv3 * vv2; acc[3][3] += pv3 * vv3;
        }
    }

    float* Ob = Cp + ((size_t)b * SS + sq0) * DM + hq * DHn;
#pragma unroll
    for (int i = 0; i < 4; i++) {
        float inv = 1.0f / l[i];
#pragma unroll
        for (int j = 0; j < 4; j++)
            Ob[(size_t)(ty * 4 + i) * DM + tx + 16 * j] = acc[i][j] * inv;
    }
}

// ---------------------------------------------------------------------------
extern "C" void kernel_launch(void* const* d_in, const int* in_sizes, int n_in,
                              void* d_out, int out_size)
{
    const float* q  = (const float*)d_in[0];
    const float* k  = (const float*)d_in[1];
    const float* v  = (const float*)d_in[2];
    const float* Wq = (const float*)d_in[3];
    const float* Wk = (const float*)d_in[4];
    const float* Wv = (const float*)d_in[5];
    const float* Wo = (const float*)d_in[6];
    float* out = (float*)d_out;

    float *Qd, *Kd, *Vd, *Cd;
    __nv_bfloat16 *Whi, *Wlo;
    cudaGetSymbolAddress((void**)&Qd, g_Q);
    cudaGetSymbolAddress((void**)&Kd, g_K);
    cudaGetSymbolAddress((void**)&Vd, g_V);
    cudaGetSymbolAddress((void**)&Cd, g_C);
    cudaGetSymbolAddress((void**)&Whi, g_Whi);
    cudaGetSymbolAddress((void**)&Wlo, g_Wlo);

    cudaFuncSetAttribute(gemm_hmma, cudaFuncAttributeMaxDynamicSharedMemorySize, GEMM_SMEM);

    dim3 wblk(32, 8);

    wconv<<<dim3(DM / 32, KDIM / 32), wblk>>>(Wq, Whi, Wlo, DM);
    gemm_hmma<<<dim3(DM / 128, ROWS / 128), 256, GEMM_SMEM>>>(q, Whi, Wlo, Qd, DM);

    wconv<<<dim3(DKV / 32, KDIM / 32), wblk>>>(Wk, Whi, Wlo, DKV);
    gemm_hmma<<<dim3(DKV / 128, ROWS / 128), 256, GEMM_SMEM>>>(k, Whi, Wlo, Kd, DKV);

    wconv<<<dim3(DKV / 32, KDIM / 32), wblk>>>(Wv, Whi, Wlo, DKV);
    gemm_hmma<<<dim3(DKV / 128, ROWS / 128), 256, GEMM_SMEM>>>(v, Whi, Wlo, Vd, DKV);

    attn64<<<dim3(SS / 64, BB * HQn), 256>>>(Qd, Kd, Vd, Cd);

    wconv<<<dim3(DM / 32, KDIM / 32), wblk>>>(Wo, Whi, Wlo, DM);
    gemm_hmma<<<dim3(DM / 128, ROWS / 128), 256, GEMM_SMEM>>>(Cd, Whi, Wlo, out, DM);
}

// round 4
// speedup vs baseline: 3.3519x; 2.2871x over previous
#include <cuda_runtime.h>
#include <cuda_bf16.h>
#include <cstdint>
#include <math.h>

#define BB   2
#define SS   2048
#define DM   2048
#define HQn  32
#define HKVn 8
#define DHn  64
#define ROWS (BB * SS)          // 4096
#define DKV  (HKVn * DHn)       // 512
#define KDIM 2048

#define SCALE_Q (0.125f * 1.44269504088896340736f)   // 1/sqrt(64) * log2(e)

// ---------------- scratch ----------------
__device__ float g_C[ROWS * DM];                       // attention context (fp32)
__device__ __nv_bfloat16 g_Whi[DM * DM];               // transposed weight hi [N][K]
__device__ __nv_bfloat16 g_Wlo[DM * DM];               // transposed weight lo [N][K]
__device__ __nv_bfloat16 g_Qh[BB * HQn * SS * DHn];    // [b,hq,s,d]
__device__ __nv_bfloat16 g_Ql[BB * HQn * SS * DHn];
__device__ __nv_bfloat16 g_Kh[BB * HKVn * SS * DHn];   // [b,hk,s,d]
__device__ __nv_bfloat16 g_Kl[BB * HKVn * SS * DHn];
__device__ __nv_bfloat16 g_Vh[BB * HKVn * SS * DHn];
__device__ __nv_bfloat16 g_Vl[BB * HKVn * SS * DHn];

// ---------------- helpers ----------------
__device__ __forceinline__ uint32_t smem_u32(const void* p) {
    uint32_t r;
    asm("{ .reg .u64 t; cvta.to.shared.u64 t, %1; cvt.u32.u64 %0, t; }" : "=r"(r) : "l"(p));
    return r;
}
__device__ __forceinline__ uint32_t packbf(float x0, float x1) {
    uint32_t r;   // mem order: low half = x0
    asm("cvt.rn.bf16x2.f32 %0, %1, %2;" : "=r"(r) : "f"(x1), "f"(x0));
    return r;
}
__device__ __forceinline__ void sts64(uint32_t a, uint32_t x, uint32_t y) {
    asm volatile("st.shared.v2.b32 [%0], {%1,%2};" :: "r"(a), "r"(x), "r"(y));
}
__device__ __forceinline__ void sts128(uint32_t a, uint4 v) {
    asm volatile("st.shared.v4.b32 [%0], {%1,%2,%3,%4};"
                 :: "r"(a), "r"(v.x), "r"(v.y), "r"(v.z), "r"(v.w));
}
__device__ __forceinline__ void ldsm4(uint32_t a, uint32_t r[4]) {
    asm volatile("ldmatrix.sync.aligned.m8n8.x4.shared.b16 {%0,%1,%2,%3}, [%4];"
                 : "=r"(r[0]), "=r"(r[1]), "=r"(r[2]), "=r"(r[3]) : "r"(a));
}
__device__ __forceinline__ void ldsm4t(uint32_t a, uint32_t r[4]) {
    asm volatile("ldmatrix.sync.aligned.m8n8.x4.trans.shared.b16 {%0,%1,%2,%3}, [%4];"
                 : "=r"(r[0]), "=r"(r[1]), "=r"(r[2]), "=r"(r[3]) : "r"(a));
}
__device__ __forceinline__ void mma_bf16(float c[4], const uint32_t a[4], const uint32_t b[2]) {
    asm volatile("mma.sync.aligned.m16n8k16.row.col.f32.bf16.bf16.f32 "
                 "{%0,%1,%2,%3},{%4,%5,%6,%7},{%8,%9},{%0,%1,%2,%3};"
                 : "+f"(c[0]), "+f"(c[1]), "+f"(c[2]), "+f"(c[3])
                 : "r"(a[0]), "r"(a[1]), "r"(a[2]), "r"(a[3]), "r"(b[0]), "r"(b[1]));
}
__device__ __forceinline__ void cp16(uint32_t dst, const void* src) {
    asm volatile("cp.async.cg.shared.global [%0], [%1], 16;" :: "r"(dst), "l"(src));
}
#define CP_COMMIT() asm volatile("cp.async.commit_group;" ::: "memory")
template<int N> __device__ __forceinline__ void cp_wait() {
    asm volatile("cp.async.wait_group %0;" :: "n"(N) : "memory");
}
__device__ __forceinline__ void split_store(__nv_bfloat16* Ch, __nv_bfloat16* Cl,
                                            size_t idx, float x0, float x1) {
    float h0 = __bfloat162float(__float2bfloat16(x0));
    float h1 = __bfloat162float(__float2bfloat16(x1));
    *(uint32_t*)(Ch + idx) = packbf(x0, x1);
    *(uint32_t*)(Cl + idx) = packbf(x0 - h0, x1 - h1);
}

// ---------------------------------------------------------------------------
// Weight transpose + bf16 hi/lo split
// ---------------------------------------------------------------------------
__global__ __launch_bounds__(256)
void wconv(const float* __restrict__ W, __nv_bfloat16* __restrict__ Whi,
           __nv_bfloat16* __restrict__ Wlo, int N)
{
    __shared__ float t[32][33];
    int n0 = blockIdx.x * 32, k0 = blockIdx.y * 32;
    int tx = threadIdx.x, ty = threadIdx.y;   // 32 x 8
#pragma unroll
    for (int i = ty; i < 32; i += 8)
        t[i][tx] = W[(size_t)(k0 + i) * N + n0 + tx];
    __syncthreads();
#pragma unroll
    for (int i = ty; i < 32; i += 8) {
        float x = t[tx][i];
        __nv_bfloat16 h = __float2bfloat16(x);
        float hf = __bfloat162float(h);
        Whi[(size_t)(n0 + i) * KDIM + k0 + tx] = h;
        Wlo[(size_t)(n0 + i) * KDIM + k0 + tx] = __float2bfloat16(x - hf);
    }
}

// ---------------------------------------------------------------------------
// HMMA GEMM, 128x128 tile, BK=32, double-buffered, 3-term bf16 split.
// MODE 0: write fp32 C row-major.  MODE 1: write bf16 hi/lo split with scale
//   into head-major layout [b, head, s, d]   (head = col/64, NH heads).
// ---------------------------------------------------------------------------
#define ST_SZ   40960
#define A_OFF   0
#define AL_OFF  10240
#define BH_OFF  20480
#define BL_OFF  30720
#define GEMM_SMEM (2 * ST_SZ)   // 81920

template<int MODE, int NH>
__global__ __launch_bounds__(256)
void gemm_hmma(const float* __restrict__ A, const __nv_bfloat16* __restrict__ Bhi,
               const __nv_bfloat16* __restrict__ Blo, float* __restrict__ C,
               __nv_bfloat16* __restrict__ Ch, __nv_bfloat16* __restrict__ Cl,
               float scale, int N)
{
    extern __shared__ char smem[];
    const uint32_t sb = smem_u32(smem);
    const int tid = threadIdx.x;
    const int wid = tid >> 5, lane = tid & 31;
    const int wm = wid >> 2, wn = wid & 3;
    const int m0 = blockIdx.y * 128, n0 = blockIdx.x * 128;

    const int arow = tid >> 3, acol = (tid & 7) * 4;
    const int brow = tid >> 2, bcol = (tid & 3) * 8;

    const float* Ab = A + (size_t)(m0 + arow) * KDIM + acol;
    const __nv_bfloat16* Bhb = Bhi + (size_t)(n0 + brow) * KDIM + bcol;
    const __nv_bfloat16* Blb = Blo + (size_t)(n0 + brow) * KDIM + bcol;

    const uint32_t aRow = (uint32_t)(wm * 64 + (lane & 15)) * 80 + (lane >> 4) * 16;
    const uint32_t bRow = (uint32_t)(wn * 32 + (lane & 7) + (lane >> 4) * 8) * 80
                        + ((lane >> 3) & 1) * 16;

    float acc[4][4][4];
#pragma unroll
    for (int i = 0; i < 4; i++)
#pragma unroll
        for (int j = 0; j < 4; j++)
#pragma unroll
            for (int r = 0; r < 4; r++) acc[i][j][r] = 0.0f;

    float4 fa[4];
    uint4  fbh[2], fbl[2];

#pragma unroll
    for (int p = 0; p < 4; p++) fa[p] = *(const float4*)(Ab + (size_t)(p * 32) * KDIM);
#pragma unroll
    for (int p = 0; p < 2; p++) {
        fbh[p] = *(const uint4*)(Bhb + (size_t)(p * 64) * KDIM);
        fbl[p] = *(const uint4*)(Blb + (size_t)(p * 64) * KDIM);
    }

    auto store_stage = [&](uint32_t st) {
#pragma unroll
        for (int p = 0; p < 4; p++) {
            uint32_t ad = st + (uint32_t)(arow + p * 32) * 80 + acol * 2;
            float x0 = fa[p].x, x1 = fa[p].y, x2 = fa[p].z, x3 = fa[p].w;
            float h0 = __bfloat162float(__float2bfloat16(x0));
            float h1 = __bfloat162float(__float2bfloat16(x1));
            float h2 = __bfloat162float(__float2bfloat16(x2));
            float h3 = __bfloat162float(__float2bfloat16(x3));
            sts64(ad + A_OFF,  packbf(x0, x1), packbf(x2, x3));
            sts64(ad + AL_OFF, packbf(x0 - h0, x1 - h1), packbf(x2 - h2, x3 - h3));
        }
#pragma unroll
        for (int p = 0; p < 2; p++) {
            uint32_t bd = st + (uint32_t)(brow + p * 64) * 80 + bcol * 2;
            sts128(bd + BH_OFF, fbh[p]);
            sts128(bd + BL_OFF, fbl[p]);
        }
    };

    store_stage(sb);
    __syncthreads();

    const int NIT = KDIM / 32;
    for (int c = 0; c < NIT; c++) {
        const uint32_t st = sb + (uint32_t)(c & 1) * ST_SZ;

        if (c + 1 < NIT) {
            int kc = (c + 1) * 32;
#pragma unroll
            for (int p = 0; p < 4; p++)
                fa[p] = *(const float4*)(Ab + (size_t)(p * 32) * KDIM + kc);
#pragma unroll
            for (int p = 0; p < 2; p++) {
                fbh[p] = *(const uint4*)(Bhb + (size_t)(p * 64) * KDIM + kc);
                fbl[p] = *(const uint4*)(Blb + (size_t)(p * 64) * KDIM + kc);
            }
        }

#pragma unroll
        for (int ks = 0; ks < 2; ks++) {
            const uint32_t ko = ks * 32;
            uint32_t ah[4][4], bh[4][2], tmpv[4];
#pragma unroll
            for (int mi = 0; mi < 4; mi++)
                ldsm4(st + A_OFF + aRow + mi * 1280 + ko, ah[mi]);
#pragma unroll
            for (int j = 0; j < 2; j++) {
                ldsm4(st + BH_OFF + bRow + j * 1280 + ko, tmpv);
                bh[2*j][0] = tmpv[0]; bh[2*j][1] = tmpv[1];
                bh[2*j+1][0] = tmpv[2]; bh[2*j+1][1] = tmpv[3];
            }
#pragma unroll
            for (int mi = 0; mi < 4; mi++)
#pragma unroll
                for (int nj = 0; nj < 4; nj++)
                    mma_bf16(acc[mi][nj], ah[mi], bh[nj]);

            uint32_t bl[4][2];
#pragma unroll
            for (int j = 0; j < 2; j++) {
                ldsm4(st + BL_OFF + bRow + j * 1280 + ko, tmpv);
                bl[2*j][0] = tmpv[0]; bl[2*j][1] = tmpv[1];
                bl[2*j+1][0] = tmpv[2]; bl[2*j+1][1] = tmpv[3];
            }
#pragma unroll
            for (int mi = 0; mi < 4; mi++)
#pragma unroll
                for (int nj = 0; nj < 4; nj++)
                    mma_bf16(acc[mi][nj], ah[mi], bl[nj]);

            uint32_t al[4][4];
#pragma unroll
            for (int mi = 0; mi < 4; mi++)
                ldsm4(st + AL_OFF + aRow + mi * 1280 + ko, al[mi]);
#pragma unroll
            for (int mi = 0; mi < 4; mi++)
#pragma unroll
                for (int nj = 0; nj < 4; nj++)
                    mma_bf16(acc[mi][nj], al[mi], bh[nj]);
        }

        if (c + 1 < NIT) store_stage(sb + (uint32_t)((c + 1) & 1) * ST_SZ);
        __syncthreads();
    }

    const int rbase = m0 + wm * 64 + (lane >> 2);
    const int cbase = n0 + wn * 32 + (lane & 3) * 2;
#pragma unroll
    for (int mi = 0; mi < 4; mi++)
#pragma unroll
        for (int nj = 0; nj < 4; nj++) {
            int r0 = rbase + mi * 16;
            int cc = cbase + nj * 8;
            if (MODE == 0) {
                *(float2*)(C + (size_t)r0 * N + cc)       = make_float2(acc[mi][nj][0], acc[mi][nj][1]);
                *(float2*)(C + (size_t)(r0 + 8) * N + cc) = make_float2(acc[mi][nj][2], acc[mi][nj][3]);
            } else {
                int bb0 = r0 >> 11, ss0 = r0 & 2047;
                int hh = cc >> 6, dd = cc & 63;
                size_t i0 = (((size_t)(bb0 * NH + hh)) * SS + ss0) * 64 + dd;
                int r1 = r0 + 8;
                int bb1 = r1 >> 11, ss1 = r1 & 2047;
                size_t i1 = (((size_t)(bb1 * NH + hh)) * SS + ss1) * 64 + dd;
                split_store(Ch, Cl, i0, acc[mi][nj][0] * scale, acc[mi][nj][1] * scale);
                split_store(Ch, Cl, i1, acc[mi][nj][2] * scale, acc[mi][nj][3] * scale);
            }
        }
}

// ---------------------------------------------------------------------------
// HMMA flash attention. Block: 256 thr (8 warps), q-tile 128, kv-tile 64.
// Warp w owns q rows w*16..w*16+15 x all 64 keys (no cross-warp softmax).
// K/V bf16 hi/lo double-buffered via cp.async. Q frags register-resident.
// ---------------------------------------------------------------------------
#define AT_STRIDE 144          // bytes per 64-elem bf16 row (+16B pad)
#define AT_KH 0
#define AT_KL 9216
#define AT_VH 18432
#define AT_VL 27648
#define AT_STAGE 36864
#define ATT_SMEM (2 * AT_STAGE)   // 73728

__global__ __launch_bounds__(256, 1)
void attn_mma(const __nv_bfloat16* __restrict__ Qh_, const __nv_bfloat16* __restrict__ Ql_,
              const __nv_bfloat16* __restrict__ Kh_, const __nv_bfloat16* __restrict__ Kl_,
              const __nv_bfloat16* __restrict__ Vh_, const __nv_bfloat16* __restrict__ Vl_,
              float* __restrict__ Cp)
{
    extern __shared__ char smem[];
    const uint32_t sb = smem_u32(smem);
    const int tid = threadIdx.x, wid = tid >> 5, lane = tid & 31;
    const int bh = blockIdx.y;
    const int b = bh >> 5, hq = bh & 31, hk = hq >> 2;
    const int q0 = blockIdx.x * 128;

    const __nv_bfloat16* Qhb = Qh_ + ((size_t)bh * SS + q0) * 64;
    const __nv_bfloat16* Qlb = Ql_ + ((size_t)bh * SS + q0) * 64;
    const size_t kvoff = (size_t)(b * HKVn + hk) * SS * 64;
    const __nv_bfloat16* Khb = Kh_ + kvoff;
    const __nv_bfloat16* Klb = Kl_ + kvoff;
    const __nv_bfloat16* Vhb = Vh_ + kvoff;
    const __nv_bfloat16* Vlb = Vl_ + kvoff;

    // ---- stage Q through smem, ldsm into register frags ----
    for (int i = tid; i < 1024; i += 256) {
        int r = i >> 3, ch = i & 7;
        *(uint4*)(smem + r * AT_STRIDE + ch * 16)         = *(const uint4*)(Qhb + (size_t)r * 64 + ch * 8);
        *(uint4*)(smem + 18432 + r * AT_STRIDE + ch * 16) = *(const uint4*)(Qlb + (size_t)r * 64 + ch * 8);
    }
    __syncthreads();

    uint32_t qh[4][4], ql[4][4];
    {
        uint32_t aAddr = sb + (uint32_t)(wid * 16 + (lane & 15)) * AT_STRIDE + (lane >> 4) * 16;
#pragma unroll
        for (int kc = 0; kc < 4; kc++) {
            ldsm4(aAddr + kc * 32, qh[kc]);
            ldsm4(aAddr + 18432 + kc * 32, ql[kc]);
        }
    }
    __syncthreads();

    // ---- async loader for one kv tile into stage st ----
    auto load_tile = [&](int kt, uint32_t st) {
        size_t base = (size_t)kt * 64 * 64;
#pragma unroll
        for (int i = tid; i < 512; i += 256) {
            int r = i >> 3, ch = i & 7;
            uint32_t d = st + r * AT_STRIDE + ch * 16;
            size_t s = base + (size_t)r * 64 + ch * 8;
            cp16(d + AT_KH, Khb + s);
            cp16(d + AT_KL, Klb + s);
            cp16(d + AT_VH, Vhb + s);
            cp16(d + AT_VL, Vlb + s);
        }
    };

    float m0 = -1e30f, m1 = -1e30f, l0 = 0.0f, l1 = 0.0f;
    float ctx[8][4];
#pragma unroll
    for (int j = 0; j < 8; j++)
#pragma unroll
        for (int e = 0; e < 4; e++) ctx[j][e] = 0.0f;

    load_tile(0, sb);
    CP_COMMIT();

    const int NKT = SS / 64;   // 32
    for (int kt = 0; kt < NKT; kt++) {
        const uint32_t st = sb + (uint32_t)(kt & 1) * AT_STAGE;
        if (kt + 1 < NKT) {
            load_tile(kt + 1, sb + (uint32_t)((kt + 1) & 1) * AT_STAGE);
            CP_COMMIT();
            cp_wait<1>();
        } else {
            cp_wait<0>();
        }
        __syncthreads();

        // ---- S = Q @ K^T (3-term split), S in log2 units ----
        float sS[8][4];
#pragma unroll
        for (int j = 0; j < 8; j++)
#pragma unroll
            for (int e = 0; e < 4; e++) sS[j][e] = 0.0f;

        const uint32_t kAddr = st + (uint32_t)((lane >> 4) * 8 + (lane & 7)) * AT_STRIDE
                             + ((lane >> 3) & 1) * 16;
#pragma unroll
        for (int kc = 0; kc < 4; kc++) {
            uint32_t bKh[8][2], bKl[8][2], t[4];
#pragma unroll
            for (int np = 0; np < 4; np++) {
                ldsm4(kAddr + AT_KH + np * 2304 + kc * 32, t);
                bKh[2*np][0] = t[0]; bKh[2*np][1] = t[1];
                bKh[2*np+1][0] = t[2]; bKh[2*np+1][1] = t[3];
                ldsm4(kAddr + AT_KL + np * 2304 + kc * 32, t);
                bKl[2*np][0] = t[0]; bKl[2*np][1] = t[1];
                bKl[2*np+1][0] = t[2]; bKl[2*np+1][1] = t[3];
            }
#pragma unroll
            for (int nj = 0; nj < 8; nj++) mma_bf16(sS[nj], qh[kc], bKh[nj]);
#pragma unroll
            for (int nj = 0; nj < 8; nj++) mma_bf16(sS[nj], ql[kc], bKh[nj]);
#pragma unroll
            for (int nj = 0; nj < 8; nj++) mma_bf16(sS[nj], qh[kc], bKl[nj]);
        }

        // ---- online softmax (base 2) ----
        float mx0 = -1e30f, mx1 = -1e30f;
#pragma unroll
        for (int j = 0; j < 8; j++) {
            mx0 = fmaxf(mx0, fmaxf(sS[j][0], sS[j][1]));
            mx1 = fmaxf(mx1, fmaxf(sS[j][2], sS[j][3]));
        }
        mx0 = fmaxf(mx0, __shfl_xor_sync(0xffffffffu, mx0, 1));
        mx0 = fmaxf(mx0, __shfl_xor_sync(0xffffffffu, mx0, 2));
        mx1 = fmaxf(mx1, __shfl_xor_sync(0xffffffffu, mx1, 1));
        mx1 = fmaxf(mx1, __shfl_xor_sync(0xffffffffu, mx1, 2));

        float mn0 = fmaxf(m0, mx0), mn1 = fmaxf(m1, mx1);
        float al0 = exp2f(m0 - mn0), al1 = exp2f(m1 - mn1);
        m0 = mn0; m1 = mn1;

        float rs0 = 0.0f, rs1 = 0.0f;
#pragma unroll
        for (int j = 0; j < 8; j++) {
            sS[j][0] = exp2f(sS[j][0] - mn0);
            sS[j][1] = exp2f(sS[j][1] - mn0);
            sS[j][2] = exp2f(sS[j][2] - mn1);
            sS[j][3] = exp2f(sS[j][3] - mn1);
            rs0 += sS[j][0] + sS[j][1];
            rs1 += sS[j][2] + sS[j][3];
        }
        rs0 += __shfl_xor_sync(0xffffffffu, rs0, 1);
        rs0 += __shfl_xor_sync(0xffffffffu, rs0, 2);
        rs1 += __shfl_xor_sync(0xffffffffu, rs1, 1);
        rs1 += __shfl_xor_sync(0xffffffffu, rs1, 2);
        l0 = l0 * al0 + rs0;
        l1 = l1 * al1 + rs1;

#pragma unroll
        for (int j = 0; j < 8; j++) {
            ctx[j][0] *= al0; ctx[j][1] *= al0;
            ctx[j][2] *= al1; ctx[j][3] *= al1;
        }

        // ---- ctx += P @ V (3-term split) ----
        const uint32_t vAddr = st + AT_VH + (uint32_t)(lane & 15) * AT_STRIDE + (lane >> 4) * 16;
#pragma unroll
        for (int kc = 0; kc < 4; kc++) {
            float x0 = sS[2*kc][0],   x1 = sS[2*kc][1],   x2 = sS[2*kc][2],   x3 = sS[2*kc][3];
            float y0 = sS[2*kc+1][0], y1 = sS[2*kc+1][1], y2 = sS[2*kc+1][2], y3 = sS[2*kc+1][3];
            uint32_t aPh[4], aPl[4];
            aPh[0] = packbf(x0, x1); aPh[1] = packbf(x2, x3);
            aPh[2] = packbf(y0, y1); aPh[3] = packbf(y2, y3);
            float hx0 = __bfloat162float(__float2bfloat16(x0));
            float hx1 = __bfloat162float(__float2bfloat16(x1));
            float hx2 = __bfloat162float(__float2bfloat16(x2));
            float hx3 = __bfloat162float(__float2bfloat16(x3));
            float hy0 = __bfloat162float(__float2bfloat16(y0));
            float hy1 = __bfloat162float(__float2bfloat16(y1));
            float hy2 = __bfloat162float(__float2bfloat16(y2));
            float hy3 = __bfloat162float(__float2bfloat16(y3));
            aPl[0] = packbf(x0 - hx0, x1 - hx1); aPl[1] = packbf(x2 - hx2, x3 - hx3);
            aPl[2] = packbf(y0 - hy0, y1 - hy1); aPl[3] = packbf(y2 - hy2, y3 - hy3);

#pragma unroll
            for (int dp = 0; dp < 4; dp++) {
                uint32_t t[4];
                ldsm4t(vAddr + kc * 2304 + dp * 32, t);
                uint32_t b0[2] = { t[0], t[1] }, b1[2] = { t[2], t[3] };
                mma_bf16(ctx[2*dp],   aPh, b0);
                mma_bf16(ctx[2*dp+1], aPh, b1);
                mma_bf16(ctx[2*dp],   aPl, b0);
                mma_bf16(ctx[2*dp+1], aPl, b1);
                ldsm4t(vAddr + (AT_VL - AT_VH) + kc * 2304 + dp * 32, t);
                uint32_t c0[2] = { t[0], t[1] }, c1[2] = { t[2], t[3] };
                mma_bf16(ctx[2*dp],   aPh, c0);
                mma_bf16(ctx[2*dp+1], aPh, c1);
            }
        }
        __syncthreads();
    }

    // ---- epilogue: normalize, write ctx fp32 [b, s, hq*64+d] ----
    float inv0 = 1.0f / l0, inv1 = 1.0f / l1;
    int r0 = q0 + wid * 16 + (lane >> 2);
    float* Ob = Cp + (size_t)b * SS * DM + (size_t)hq * 64;
#pragma unroll
    for (int nj = 0; nj < 8; nj++) {
        int cc = nj * 8 + (lane & 3) * 2;
        *(float2*)(Ob + (size_t)r0 * DM + cc)       = make_float2(ctx[nj][0] * inv0, ctx[nj][1] * inv0);
        *(float2*)(Ob + (size_t)(r0 + 8) * DM + cc) = make_float2(ctx[nj][2] * inv1, ctx[nj][3] * inv1);
    }
}

// ---------------------------------------------------------------------------
extern "C" void kernel_launch(void* const* d_in, const int* in_sizes, int n_in,
                              void* d_out, int out_size)
{
    const float* q  = (const float*)d_in[0];
    const float* k  = (const float*)d_in[1];
    const float* v  = (const float*)d_in[2];
    const float* Wq = (const float*)d_in[3];
    const float* Wk = (const float*)d_in[4];
    const float* Wv = (const float*)d_in[5];
    const float* Wo = (const float*)d_in[6];
    float* out = (float*)d_out;

    float *Cd;
    __nv_bfloat16 *Whi, *Wlo, *Qh, *Ql, *Kh, *Kl, *Vh, *Vl;
    cudaGetSymbolAddress((void**)&Cd, g_C);
    cudaGetSymbolAddress((void**)&Whi, g_Whi);
    cudaGetSymbolAddress((void**)&Wlo, g_Wlo);
    cudaGetSymbolAddress((void**)&Qh, g_Qh);
    cudaGetSymbolAddress((void**)&Ql, g_Ql);
    cudaGetSymbolAddress((void**)&Kh, g_Kh);
    cudaGetSymbolAddress((void**)&Kl, g_Kl);
    cudaGetSymbolAddress((void**)&Vh, g_Vh);
    cudaGetSymbolAddress((void**)&Vl, g_Vl);

    cudaFuncSetAttribute((const void*)&gemm_hmma<0,0>,  cudaFuncAttributeMaxDynamicSharedMemorySize, GEMM_SMEM);
    cudaFuncSetAttribute((const void*)&gemm_hmma<1,32>, cudaFuncAttributeMaxDynamicSharedMemorySize, GEMM_SMEM);
    cudaFuncSetAttribute((const void*)&gemm_hmma<1,8>,  cudaFuncAttributeMaxDynamicSharedMemorySize, GEMM_SMEM);
    cudaFuncSetAttribute((const void*)&attn_mma,        cudaFuncAttributeMaxDynamicSharedMemorySize, ATT_SMEM);

    dim3 wblk(32, 8);

    wconv<<<dim3(DM / 32, KDIM / 32), wblk>>>(Wq, Whi, Wlo, DM);
    gemm_hmma<1,32><<<dim3(DM / 128, ROWS / 128), 256, GEMM_SMEM>>>(
        q, Whi, Wlo, nullptr, Qh, Ql, SCALE_Q, DM);

    wconv<<<dim3(DKV / 32, KDIM / 32), wblk>>>(Wk, Whi, Wlo, DKV);
    gemm_hmma<1,8><<<dim3(DKV / 128, ROWS / 128), 256, GEMM_SMEM>>>(
        k, Whi, Wlo, nullptr, Kh, Kl, 1.0f, DKV);

    wconv<<<dim3(DKV / 32, KDIM / 32), wblk>>>(Wv, Whi, Wlo, DKV);
    gemm_hmma<1,8><<<dim3(DKV / 128, ROWS / 128), 256, GEMM_SMEM>>>(
        v, Whi, Wlo, nullptr, Vh, Vl, 1.0f, DKV);

    attn_mma<<<dim3(SS / 128, BB * HQn), 256, ATT_SMEM>>>(Qh, Ql, Kh, Kl, Vh, Vl, Cd);

    wconv<<<dim3(DM / 32, KDIM / 32), wblk>>>(Wo, Whi, Wlo, DM);
    gemm_hmma<0,0><<<dim3(DM / 128, ROWS / 128), 256, GEMM_SMEM>>>(
        Cd, Whi, Wlo, out, nullptr, nullptr, 1.0f, DM);
}